// round 12
// baseline (speedup 1.0000x reference)
#include <cuda_runtime.h>
#include <cuda.h>
#include <cuda_fp16.h>
#include <cstdint>

#define NNB 32
#define CI  128
#define CO  256
#define HH  56
#define WW  56

// Padded NHWC x in fp16: [n][59 rows][64 cols][128 ci]; rows 1..56 = h 0..55,
// cols 0..55 = w, all padding zero. 128-half front guard for the (h0=0, col -1) read.
__device__ __align__(256) __half g_xt[128 + (size_t)NNB * 59 * 64 * CI];
__device__ __align__(256) __half g_wt[9 * CO * CI];   // [tap][co][ci]
__device__ unsigned g_ticket;                          // persistent-CTA work counter

// ---------------- helpers ----------------
__device__ __forceinline__ void cp_async16(uint32_t dst_smem, const void* src) {
    asm volatile("cp.async.cg.shared.global [%0], [%1], 16;" :: "r"(dst_smem), "l"(src) : "memory");
}
#define CP_COMMIT() asm volatile("cp.async.commit_group;" ::: "memory")
#define CP_WAIT0()  asm volatile("cp.async.wait_group 0;" ::: "memory")

#define LDM_X4(r0, r1, r2, r3, addr) \
    asm volatile("ldmatrix.sync.aligned.m8n8.x4.shared.b16 {%0,%1,%2,%3}, [%4];" \
        : "=r"(r0), "=r"(r1), "=r"(r2), "=r"(r3) : "r"(addr))
#define LDM_X2(r0, r1, addr) \
    asm volatile("ldmatrix.sync.aligned.m8n8.x2.shared.b16 {%0,%1}, [%2];" \
        : "=r"(r0), "=r"(r1) : "r"(addr))

__device__ __forceinline__ void mma_f16(float d[4], const uint32_t a[4], uint32_t b0, uint32_t b1) {
    asm volatile(
        "mma.sync.aligned.m16n8k16.row.col.f32.f16.f16.f32 "
        "{%0,%1,%2,%3}, {%4,%5,%6,%7}, {%8,%9}, {%0,%1,%2,%3};"
        : "+f"(d[0]), "+f"(d[1]), "+f"(d[2]), "+f"(d[3])
        : "r"(a[0]), "r"(a[1]), "r"(a[2]), "r"(a[3]), "r"(b0), "r"(b1));
}

// ---------------- fused prologue (round-8 version, known good) ----------------
__global__ __launch_bounds__(256)
void prologue_kernel(const float* __restrict__ x, const float* __restrict__ wgt) {
    const int tid = threadIdx.x;
    const int n   = blockIdx.y;

    if (blockIdx.x == 59) {   // weights
        if (n == 0 && tid == 0) g_ticket = 0u;   // reset work counter each launch
        const int base = n * (9 * CO * CI / NNB);
        for (int k = 0; k < 9 * CO * CI / NNB; k += 256) {
            int idx = base + k + tid;
            int ci  = idx % CI;
            int t   = idx / CI;
            int co  = t % CO;
            int tap = t / CO;
            g_wt[idx] = __float2half_rn(wgt[((size_t)co * CI + ci) * 9 + tap]);
        }
        return;
    }

    __shared__ float s[128][57];
    const int h_p = blockIdx.x;     // 0..58
    const int h   = h_p - 1;
    const bool valid = (h >= 0) && (h < HH);

    if (h_p == 0 && n == 0 && tid < 16)
        *(uint4*)(g_xt + tid * 8) = make_uint4(0u, 0u, 0u, 0u);

    if (valid) {
        for (int idx = tid; idx < CI * WW; idx += 256) {
            int ci = idx / WW, w = idx % WW;
            s[ci][w] = x[(((size_t)n * CI + ci) * HH + h) * WW + w];
        }
    }
    __syncthreads();

    __half* dst = g_xt + 128 + (size_t)(n * 59 + h_p) * 64 * CI;
    for (int idx = tid; idx < 64 * 16; idx += 256) {
        const int w = idx >> 4;
        const int g = idx & 15;
        uint4 v = make_uint4(0u, 0u, 0u, 0u);
        if (valid && w < WW) {
            __half2 p0 = __floats2half2_rn(s[g * 8 + 0][w], s[g * 8 + 1][w]);
            __half2 p1 = __floats2half2_rn(s[g * 8 + 2][w], s[g * 8 + 3][w]);
            __half2 p2 = __floats2half2_rn(s[g * 8 + 4][w], s[g * 8 + 5][w]);
            __half2 p3 = __floats2half2_rn(s[g * 8 + 6][w], s[g * 8 + 7][w]);
            v.x = *(uint32_t*)&p0; v.y = *(uint32_t*)&p1;
            v.z = *(uint32_t*)&p2; v.w = *(uint32_t*)&p3;
        }
        *(uint4*)(dst + (size_t)w * CI + g * 8) = v;
    }
}

// ---------------- persistent main kernel ----------------
// 296 CTAs (2/SM); tiles claimed via atomic ticket. Per tile: identical to the
// round-10 dense 128co x 112px chunk loop. Next tile's B+A0 cp.async is issued
// BEFORE the epilogue, hiding the 80KB preload behind the output stores.
constexpr int NTILES = (CO / 128) * (HH / 2) * NNB;   // 1792
constexpr int B_HALF_BYTES = 250 * 128;               // 32000
constexpr int B_BYTES      = 2 * B_HALF_BYTES;        // 64000
constexpr int A_TILE       = 128 * 64 * 2;            // 16384
constexpr int SMEM_BYTES   = B_BYTES + 2 * A_TILE;    // 96768

__global__ __launch_bounds__(128, 2)
void conv_mma_kernel(float* __restrict__ out)
{
    extern __shared__ char smem[];
    const uint32_t sm_u = (uint32_t)__cvta_generic_to_shared(smem);
    const uint32_t B_u  = sm_u;
    const uint32_t A_u  = sm_u + B_BYTES;

    const int tid  = threadIdx.x;
    const int lane = tid & 31;
    const int warp = tid >> 5;
    const int g    = lane >> 2;
    const int t    = lane & 3;
    const int warp_m = (warp >> 1) * 64;
    const int warp_n = (warp & 1) * 56;

    const __half* xb = g_xt + 128;

    const int quad  = lane >> 3;
    const int rowin = lane & 7;
    const int qlow  = quad & 1;
    const int qhigh = quad >> 1;

    uint32_t aRowB[4];
    #pragma unroll
    for (int mi = 0; mi < 4; mi++)
        aRowB[mi] = (uint32_t)(warp_m + mi * 16 + qlow * 8 + rowin) * 128u;

    uint32_t bRowB[4];
    #pragma unroll
    for (int p = 0; p < 3; p++) {
        const int px = warp_n + (p * 2 + qhigh) * 8 + rowin;
        bRowB[p] = (uint32_t)(px + 8 * (px / 56)) * 128u;
    }
    {
        const int px7 = warp_n + 48 + rowin;
        bRowB[3] = (uint32_t)(px7 + 8 * (px7 / 56)) * 128u;
    }

    __shared__ unsigned s_tile;

    auto preloadB = [&](int n_, int h0_) {
        const long long F0 = ((long long)(n_ * 59 + h0_) * 64 - 1) * CI;
        #pragma unroll
        for (int half = 0; half < 2; half++) {
            const __half* src = xb + F0 + half * 64;
            const uint32_t dstb = B_u + half * B_HALF_BYTES;
            for (int idx = tid; idx < 250 * 8; idx += 128) {
                const int i = idx >> 3, c = idx & 7;
                cp_async16(dstb + (uint32_t)i * 128u + (uint32_t)((c ^ (i & 7)) * 16),
                           src + (size_t)i * CI + c * 8);
            }
        }
    };
    auto loadA = [&](int kc, int co_b) {
        const int tap = kc >> 1, cihalf = kc & 1;
        const __half* src = g_wt + (size_t)(tap * CO + co_b) * CI + cihalf * 64;
        const uint32_t dA = A_u + (kc & 1) * A_TILE;
        #pragma unroll
        for (int i = 0; i < 8; i++) {
            const int q = tid + 128 * i;
            const int row = q >> 3, c = q & 7;
            cp_async16(dA + (uint32_t)row * 128u + (uint32_t)((c ^ (row & 7)) * 16),
                       src + (size_t)row * CI + c * 8);
        }
    };

    if (tid == 0) s_tile = atomicAdd(&g_ticket, 1u);
    __syncthreads();
    unsigned tile = s_tile;
    bool pre = false;

    while (tile < (unsigned)NTILES) {
        const int co_base = (int)(tile & 1u) * 128;
        const unsigned t1 = tile >> 1;
        const int n  = (int)(t1 / 28u);
        const int h0 = (int)(t1 - (unsigned)n * 28u) * 2;

        if (!pre) {
            preloadB(n, h0);
            loadA(0, co_base);
            CP_COMMIT();
        }

        float acc[4][7][4];
        #pragma unroll
        for (int mi = 0; mi < 4; mi++)
            #pragma unroll
            for (int ni = 0; ni < 7; ni++)
                #pragma unroll
                for (int r = 0; r < 4; r++) acc[mi][ni][r] = 0.0f;

        #pragma unroll
        for (int kc = 0; kc < 18; kc++) {
            const int tap = kc >> 1, cihalf = kc & 1;
            const int r = tap / 3, s = tap % 3;
            const int off = r * 64 + s;

            CP_WAIT0();
            __syncthreads();

            const uint32_t A  = A_u + (kc & 1) * A_TILE;
            const uint32_t Bo = B_u + cihalf * B_HALF_BYTES + (uint32_t)off * 128u;
            const int ro = (rowin + off) & 7;

            #pragma unroll
            for (int kk = 0; kk < 4; kk++) {
                uint32_t a[4][4];
                #pragma unroll
                for (int mi = 0; mi < 4; mi++)
                    LDM_X4(a[mi][0], a[mi][1], a[mi][2], a[mi][3],
                           A + aRowB[mi] + (uint32_t)(((kk * 2 + qhigh) ^ rowin) * 16));
                #pragma unroll
                for (int p = 0; p < 3; p++) {
                    uint32_t b0, b1, b2, b3;
                    LDM_X4(b0, b1, b2, b3,
                           Bo + bRowB[p] + (uint32_t)(((kk * 2 + qlow) ^ ro) * 16));
                    #pragma unroll
                    for (int mi = 0; mi < 4; mi++) {
                        mma_f16(acc[mi][2 * p],     a[mi], b0, b1);
                        mma_f16(acc[mi][2 * p + 1], a[mi], b2, b3);
                    }
                }
                {
                    uint32_t b0, b1;
                    LDM_X2(b0, b1,
                           Bo + bRowB[3] + (uint32_t)(((kk * 2 + qlow) ^ ro) * 16));
                    #pragma unroll
                    for (int mi = 0; mi < 4; mi++)
                        mma_f16(acc[mi][6], a[mi], b0, b1);
                }
                if (kk == 1) {
                    if (kc + 1 < 18) loadA(kc + 1, co_base);
                    CP_COMMIT();
                }
            }
            __syncthreads();
        }

        // ---- claim next tile and prefetch its B + A0 BEFORE the epilogue
        if (tid == 0) s_tile = atomicAdd(&g_ticket, 1u);
        __syncthreads();
        const unsigned next = s_tile;
        if (next < (unsigned)NTILES) {
            const int nco = (int)(next & 1u) * 128;
            const unsigned nt1 = next >> 1;
            const int nn  = (int)(nt1 / 28u);
            const int nh0 = (int)(nt1 - (unsigned)nn * 28u) * 2;
            preloadB(nn, nh0);
            loadA(0, nco);
            CP_COMMIT();
            pre = true;
        }

        // ---- epilogue for the current tile (overlaps the prefetch above)
        #pragma unroll
        for (int mi = 0; mi < 4; mi++)
            #pragma unroll
            for (int ni = 0; ni < 7; ni++)
                #pragma unroll
                for (int half = 0; half < 2; half++) {
                    const int co = co_base + warp_m + mi * 16 + g + half * 8;
                    const int px = warp_n + ni * 8 + 2 * t;
                    const int dh = px / 56, w = px % 56;
                    float2 v = make_float2(acc[mi][ni][half * 2], acc[mi][ni][half * 2 + 1]);
                    *(float2*)&out[(((size_t)n * CO + co) * HH + (h0 + dh)) * WW + w] = v;
                }

        tile = next;
    }
}

// ---------------- host ----------------
extern "C" void kernel_launch(void* const* d_in, const int* in_sizes, int n_in,
                              void* d_out, int out_size)
{
    const float* x   = (const float*)d_in[0];
    const float* wgt = (const float*)d_in[1];
    float*       out = (float*)d_out;

    prologue_kernel<<<dim3(60, NNB), 256>>>(x, wgt);

    cudaFuncSetAttribute(conv_mma_kernel, cudaFuncAttributeMaxDynamicSharedMemorySize, SMEM_BYTES);
    conv_mma_kernel<<<296, 128, SMEM_BYTES>>>(out);
}

// round 13
// speedup vs baseline: 1.0151x; 1.0151x over previous
#include <cuda_runtime.h>
#include <cuda.h>
#include <cuda_fp16.h>
#include <cstdint>

#define NNB 32
#define CI  128
#define CO  256
#define HH  56
#define WW  56

// Padded NHWC x in fp16: [n][59 rows][64 cols][128 ci]; rows 1..56 = h 0..55,
// cols 0..55 = w, all padding zero. 128-half front guard for the (h0=0, col -1) read.
__device__ __align__(256) __half g_xt[128 + (size_t)NNB * 59 * 64 * CI];
__device__ __align__(256) __half g_wt[9 * CO * CI];   // [tap][co][ci]

// ---------------- helpers ----------------
__device__ __forceinline__ void cp_async16(uint32_t dst_smem, const void* src) {
    asm volatile("cp.async.cg.shared.global [%0], [%1], 16;" :: "r"(dst_smem), "l"(src) : "memory");
}
#define CP_COMMIT() asm volatile("cp.async.commit_group;" ::: "memory")
#define CP_WAIT0()  asm volatile("cp.async.wait_group 0;" ::: "memory")

#define LDM_X4(r0, r1, r2, r3, addr) \
    asm volatile("ldmatrix.sync.aligned.m8n8.x4.shared.b16 {%0,%1,%2,%3}, [%4];" \
        : "=r"(r0), "=r"(r1), "=r"(r2), "=r"(r3) : "r"(addr))
#define LDM_X2(r0, r1, addr) \
    asm volatile("ldmatrix.sync.aligned.m8n8.x2.shared.b16 {%0,%1}, [%2];" \
        : "=r"(r0), "=r"(r1) : "r"(addr))

__device__ __forceinline__ void mma_f16(float d[4], const uint32_t a[4], uint32_t b0, uint32_t b1) {
    asm volatile(
        "mma.sync.aligned.m16n8k16.row.col.f32.f16.f16.f32 "
        "{%0,%1,%2,%3}, {%4,%5,%6,%7}, {%8,%9}, {%0,%1,%2,%3};"
        : "+f"(d[0]), "+f"(d[1]), "+f"(d[2]), "+f"(d[3])
        : "r"(a[0]), "r"(a[1]), "r"(a[2]), "r"(a[3]), "r"(b0), "r"(b1));
}

// ---------------- fused prologue ----------------
// xpose with s[w][ci], row stride 132 floats (528B, 16B-aligned).
//  Phase 1: float4 gmem reads (lane->ci mapping), 4 scalar STS each -> banks
//           (16j + 4i + ci) & 31: distinct across 32 consecutive-ci lanes.
//  Phase 2: ld.shared.v4 of 8 consecutive ci (8-lane groups read 128B
//           contiguous -> conflict-free), pack half2, 16B coalesced stores.
constexpr int SPITCH = 132;   // floats per w-row in smem

__global__ __launch_bounds__(256)
void prologue_kernel(const float* __restrict__ x, const float* __restrict__ wgt) {
    const int tid = threadIdx.x;
    const int n   = blockIdx.y;

    if (blockIdx.x == 59) {   // weights
        const int base = n * (9 * CO * CI / NNB);
        for (int k = 0; k < 9 * CO * CI / NNB; k += 256) {
            int idx = base + k + tid;
            int ci  = idx % CI;
            int t   = idx / CI;
            int co  = t % CO;
            int tap = t / CO;
            g_wt[idx] = __float2half_rn(wgt[((size_t)co * CI + ci) * 9 + tap]);
        }
        return;
    }

    __shared__ float s[56 * SPITCH];
    const int h_p = blockIdx.x;     // 0..58
    const int h   = h_p - 1;
    const bool valid = (h >= 0) && (h < HH);

    if (h_p == 0 && n == 0 && tid < 16)   // front guard (row "-1" of n=0)
        *(uint4*)(g_xt + tid * 8) = make_uint4(0u, 0u, 0u, 0u);

    if (valid) {
        const float* base = x + ((size_t)n * CI * HH + h) * WW;
        // 128 ci x 14 float4 (56 floats) per row; lane -> ci (conflict-free STS)
        for (int idx = tid; idx < CI * 14; idx += 256) {
            const int ci = idx & 127;
            const int j  = idx >> 7;
            float4 v = *(const float4*)(base + (size_t)ci * HH * WW + 4 * j);
            s[(4 * j + 0) * SPITCH + ci] = v.x;
            s[(4 * j + 1) * SPITCH + ci] = v.y;
            s[(4 * j + 2) * SPITCH + ci] = v.z;
            s[(4 * j + 3) * SPITCH + ci] = v.w;
        }
    }
    __syncthreads();

    __half* dst = g_xt + 128 + (size_t)(n * 59 + h_p) * 64 * CI;
    for (int idx = tid; idx < 64 * 16; idx += 256) {
        const int w = idx >> 4;         // 0..63
        const int g = idx & 15;         // ci group of 8
        uint4 v = make_uint4(0u, 0u, 0u, 0u);
        if (valid && w < WW) {
            const float* sp = s + w * SPITCH + g * 8;
            float4 f0 = *(const float4*)(sp);
            float4 f1 = *(const float4*)(sp + 4);
            __half2 p0 = __floats2half2_rn(f0.x, f0.y);
            __half2 p1 = __floats2half2_rn(f0.z, f0.w);
            __half2 p2 = __floats2half2_rn(f1.x, f1.y);
            __half2 p3 = __floats2half2_rn(f1.z, f1.w);
            v.x = *(uint32_t*)&p0; v.y = *(uint32_t*)&p1;
            v.z = *(uint32_t*)&p2; v.w = *(uint32_t*)&p3;
        }
        *(uint4*)(dst + (size_t)w * CI + g * 8) = v;
    }
}

// ---------------- main kernel (FROZEN: round-10 dense-tile version) ----------------
constexpr int B_HALF_BYTES = 250 * 128;              // 32000
constexpr int B_BYTES      = 2 * B_HALF_BYTES;       // 64000
constexpr int A_TILE       = 128 * 64 * 2;           // 16384
constexpr int SMEM_BYTES   = B_BYTES + 2 * A_TILE;   // 96768

__global__ __launch_bounds__(128, 2)
void conv_mma_kernel(float* __restrict__ out)
{
    extern __shared__ char smem[];
    const uint32_t sm_u = (uint32_t)__cvta_generic_to_shared(smem);
    const uint32_t B_u  = sm_u;
    const uint32_t A_u  = sm_u + B_BYTES;

    const int tid  = threadIdx.x;
    const int lane = tid & 31;
    const int warp = tid >> 5;
    const int g    = lane >> 2;
    const int t    = lane & 3;
    const int warp_m = (warp >> 1) * 64;
    const int warp_n = (warp & 1) * 56;

    const int co_base = blockIdx.x * 128;
    const int h0      = blockIdx.y * 2;
    const int n       = blockIdx.z;

    const __half* xb = g_xt + 128;

    const int quad  = lane >> 3;
    const int rowin = lane & 7;
    const int qlow  = quad & 1;
    const int qhigh = quad >> 1;

    uint32_t aRowB[4];
    #pragma unroll
    for (int mi = 0; mi < 4; mi++)
        aRowB[mi] = (uint32_t)(warp_m + mi * 16 + qlow * 8 + rowin) * 128u;

    uint32_t bRowB[4];
    #pragma unroll
    for (int p = 0; p < 3; p++) {
        const int px = warp_n + (p * 2 + qhigh) * 8 + rowin;
        bRowB[p] = (uint32_t)(px + 8 * (px / 56)) * 128u;
    }
    {
        const int px7 = warp_n + 48 + rowin;
        bRowB[3] = (uint32_t)(px7 + 8 * (px7 / 56)) * 128u;
    }

    float acc[4][7][4];
    #pragma unroll
    for (int mi = 0; mi < 4; mi++)
        #pragma unroll
        for (int ni = 0; ni < 7; ni++)
            #pragma unroll
            for (int r = 0; r < 4; r++) acc[mi][ni][r] = 0.0f;

    {
        const long long F0 = ((long long)(n * 59 + h0) * 64 - 1) * CI;
        #pragma unroll
        for (int half = 0; half < 2; half++) {
            const __half* src = xb + F0 + half * 64;
            const uint32_t dstb = B_u + half * B_HALF_BYTES;
            for (int idx = tid; idx < 250 * 8; idx += 128) {
                const int i = idx >> 3, c = idx & 7;
                cp_async16(dstb + (uint32_t)i * 128u + (uint32_t)((c ^ (i & 7)) * 16),
                           src + (size_t)i * CI + c * 8);
            }
        }
    }

    auto loadA = [&](int kc) {
        const int tap = kc >> 1, cihalf = kc & 1;
        const __half* src = g_wt + (size_t)(tap * CO + co_base) * CI + cihalf * 64;
        const uint32_t dA = A_u + (kc & 1) * A_TILE;
        #pragma unroll
        for (int i = 0; i < 8; i++) {
            const int q = tid + 128 * i;
            const int row = q >> 3, c = q & 7;
            cp_async16(dA + (uint32_t)row * 128u + (uint32_t)((c ^ (row & 7)) * 16),
                       src + (size_t)row * CI + c * 8);
        }
    };

    loadA(0);
    CP_COMMIT();

    #pragma unroll
    for (int kc = 0; kc < 18; kc++) {
        const int tap = kc >> 1, cihalf = kc & 1;
        const int r = tap / 3, s = tap % 3;
        const int off = r * 64 + s;

        CP_WAIT0();
        __syncthreads();

        const uint32_t A  = A_u + (kc & 1) * A_TILE;
        const uint32_t Bo = B_u + cihalf * B_HALF_BYTES + (uint32_t)off * 128u;
        const int ro = (rowin + off) & 7;

        #pragma unroll
        for (int kk = 0; kk < 4; kk++) {
            uint32_t a[4][4];
            #pragma unroll
            for (int mi = 0; mi < 4; mi++)
                LDM_X4(a[mi][0], a[mi][1], a[mi][2], a[mi][3],
                       A + aRowB[mi] + (uint32_t)(((kk * 2 + qhigh) ^ rowin) * 16));
            #pragma unroll
            for (int p = 0; p < 3; p++) {
                uint32_t b0, b1, b2, b3;
                LDM_X4(b0, b1, b2, b3,
                       Bo + bRowB[p] + (uint32_t)(((kk * 2 + qlow) ^ ro) * 16));
                #pragma unroll
                for (int mi = 0; mi < 4; mi++) {
                    mma_f16(acc[mi][2 * p],     a[mi], b0, b1);
                    mma_f16(acc[mi][2 * p + 1], a[mi], b2, b3);
                }
            }
            {
                uint32_t b0, b1;
                LDM_X2(b0, b1,
                       Bo + bRowB[3] + (uint32_t)(((kk * 2 + qlow) ^ ro) * 16));
                #pragma unroll
                for (int mi = 0; mi < 4; mi++)
                    mma_f16(acc[mi][6], a[mi], b0, b1);
            }
            if (kk == 1) {
                if (kc + 1 < 18) loadA(kc + 1);
                CP_COMMIT();
            }
        }
        __syncthreads();
    }

    #pragma unroll
    for (int mi = 0; mi < 4; mi++)
        #pragma unroll
        for (int ni = 0; ni < 7; ni++)
            #pragma unroll
            for (int half = 0; half < 2; half++) {
                const int co = co_base + warp_m + mi * 16 + g + half * 8;
                const int px = warp_n + ni * 8 + 2 * t;
                const int dh = px / 56, w = px % 56;
                float2 v = make_float2(acc[mi][ni][half * 2], acc[mi][ni][half * 2 + 1]);
                *(float2*)&out[(((size_t)n * CO + co) * HH + (h0 + dh)) * WW + w] = v;
            }
}

// ---------------- host ----------------
extern "C" void kernel_launch(void* const* d_in, const int* in_sizes, int n_in,
                              void* d_out, int out_size)
{
    const float* x   = (const float*)d_in[0];
    const float* wgt = (const float*)d_in[1];
    float*       out = (float*)d_out;

    prologue_kernel<<<dim3(60, NNB), 256>>>(x, wgt);

    cudaFuncSetAttribute(conv_mma_kernel, cudaFuncAttributeMaxDynamicSharedMemorySize, SMEM_BYTES);
    conv_mma_kernel<<<dim3(2, 28, NNB), 128, SMEM_BYTES>>>(out);
}

// round 14
// speedup vs baseline: 1.0939x; 1.0777x over previous
#include <cuda_runtime.h>
#include <cuda.h>
#include <cuda_fp16.h>
#include <cstdint>

#define NNB 32
#define CI  128
#define CO  256
#define HH  56
#define WW  56

// Padded NHWC x in fp16: [n][59 rows][64 cols][128 ci]; rows 1..56 = h 0..55,
// cols 0..55 = w, all padding zero. 128-half front guard for the (h0=0, col -1) read.
__device__ __align__(256) __half g_xt[128 + (size_t)NNB * 59 * 64 * CI];
__device__ __align__(256) __half g_wt[9 * CO * CI];   // [tap][co][ci]

// ---------------- helpers ----------------
__device__ __forceinline__ void cp_async16(uint32_t dst_smem, const void* src) {
    asm volatile("cp.async.cg.shared.global [%0], [%1], 16;" :: "r"(dst_smem), "l"(src) : "memory");
}
#define CP_COMMIT() asm volatile("cp.async.commit_group;" ::: "memory")
#define CP_WAIT0()  asm volatile("cp.async.wait_group 0;" ::: "memory")

#define LDM_X4(r0, r1, r2, r3, addr) \
    asm volatile("ldmatrix.sync.aligned.m8n8.x4.shared.b16 {%0,%1,%2,%3}, [%4];" \
        : "=r"(r0), "=r"(r1), "=r"(r2), "=r"(r3) : "r"(addr))
#define LDM_X2(r0, r1, addr) \
    asm volatile("ldmatrix.sync.aligned.m8n8.x2.shared.b16 {%0,%1}, [%2];" \
        : "=r"(r0), "=r"(r1) : "r"(addr))

__device__ __forceinline__ void mma_f16(float d[4], const uint32_t a[4], uint32_t b0, uint32_t b1) {
    asm volatile(
        "mma.sync.aligned.m16n8k16.row.col.f32.f16.f16.f32 "
        "{%0,%1,%2,%3}, {%4,%5,%6,%7}, {%8,%9}, {%0,%1,%2,%3};"
        : "+f"(d[0]), "+f"(d[1]), "+f"(d[2]), "+f"(d[3])
        : "r"(a[0]), "r"(a[1]), "r"(a[2]), "r"(a[3]), "r"(b0), "r"(b1));
}

// ---------------- fused prologue ----------------
// xpose: s[ci][w + 2*(ci>>3)], pitch 87 floats.
//  Phase 1: lane->w fast (coalesced LDG along w); stores along w = consecutive
//           banks, conflict-free (per-ci column offset is constant).
//  Phase 2: thread (w,g) reads s[8g+k][w+2g], k=0..7. Bank = (26g+23k+w)%32:
//           26g injective for g<16, parity splits the two w values -> all 32
//           lanes on distinct banks, conflict-free for every k.
constexpr int SPITCH = 87;

__global__ __launch_bounds__(256)
void prologue_kernel(const float* __restrict__ x, const float* __restrict__ wgt) {
    const int tid = threadIdx.x;
    const int n   = blockIdx.y;

    if (blockIdx.x == 59) {   // weights
        const int base = n * (9 * CO * CI / NNB);
        for (int k = 0; k < 9 * CO * CI / NNB; k += 256) {
            int idx = base + k + tid;
            int ci  = idx % CI;
            int t   = idx / CI;
            int co  = t % CO;
            int tap = t / CO;
            g_wt[idx] = __float2half_rn(wgt[((size_t)co * CI + ci) * 9 + tap]);
        }
        return;
    }

    __shared__ float s[CI * SPITCH];   // s[ci][87]
    const int h_p = blockIdx.x;        // 0..58
    const int h   = h_p - 1;
    const bool valid = (h >= 0) && (h < HH);

    if (h_p == 0 && n == 0 && tid < 16)   // front guard (row "-1" of n=0)
        *(uint4*)(g_xt + tid * 8) = make_uint4(0u, 0u, 0u, 0u);

    if (valid) {
        const float* base = x + ((size_t)n * CI * HH + h) * WW;
        for (int idx = tid; idx < CI * WW; idx += 256) {
            const int ci = idx / WW, w = idx - ci * WW;   // lane -> w fast (coalesced)
            s[ci * SPITCH + w + 2 * (ci >> 3)] = base[(size_t)ci * HH * WW + w];
        }
    }
    __syncthreads();

    __half* dst = g_xt + 128 + (size_t)(n * 59 + h_p) * 64 * CI;
    for (int idx = tid; idx < 64 * 16; idx += 256) {
        const int w = idx >> 4;         // 0..63
        const int g = idx & 15;         // ci group of 8
        uint4 v = make_uint4(0u, 0u, 0u, 0u);
        if (valid && w < WW) {
            const float* sp = s + (g * 8) * SPITCH + w + 2 * g;
            float f0 = sp[0 * SPITCH], f1 = sp[1 * SPITCH];
            float f2 = sp[2 * SPITCH], f3 = sp[3 * SPITCH];
            float f4 = sp[4 * SPITCH], f5 = sp[5 * SPITCH];
            float f6 = sp[6 * SPITCH], f7 = sp[7 * SPITCH];
            __half2 p0 = __floats2half2_rn(f0, f1);
            __half2 p1 = __floats2half2_rn(f2, f3);
            __half2 p2 = __floats2half2_rn(f4, f5);
            __half2 p3 = __floats2half2_rn(f6, f7);
            v.x = *(uint32_t*)&p0; v.y = *(uint32_t*)&p1;
            v.z = *(uint32_t*)&p2; v.w = *(uint32_t*)&p3;
        }
        *(uint4*)(dst + (size_t)w * CI + g * 8) = v;
    }
}

// ---------------- main kernel (FROZEN: round-10 dense-tile version) ----------------
constexpr int B_HALF_BYTES = 250 * 128;              // 32000
constexpr int B_BYTES      = 2 * B_HALF_BYTES;       // 64000
constexpr int A_TILE       = 128 * 64 * 2;           // 16384
constexpr int SMEM_BYTES   = B_BYTES + 2 * A_TILE;   // 96768

__global__ __launch_bounds__(128, 2)
void conv_mma_kernel(float* __restrict__ out)
{
    extern __shared__ char smem[];
    const uint32_t sm_u = (uint32_t)__cvta_generic_to_shared(smem);
    const uint32_t B_u  = sm_u;
    const uint32_t A_u  = sm_u + B_BYTES;

    const int tid  = threadIdx.x;
    const int lane = tid & 31;
    const int warp = tid >> 5;
    const int g    = lane >> 2;
    const int t    = lane & 3;
    const int warp_m = (warp >> 1) * 64;
    const int warp_n = (warp & 1) * 56;

    const int co_base = blockIdx.x * 128;
    const int h0      = blockIdx.y * 2;
    const int n       = blockIdx.z;

    const __half* xb = g_xt + 128;

    const int quad  = lane >> 3;
    const int rowin = lane & 7;
    const int qlow  = quad & 1;
    const int qhigh = quad >> 1;

    uint32_t aRowB[4];
    #pragma unroll
    for (int mi = 0; mi < 4; mi++)
        aRowB[mi] = (uint32_t)(warp_m + mi * 16 + qlow * 8 + rowin) * 128u;

    uint32_t bRowB[4];
    #pragma unroll
    for (int p = 0; p < 3; p++) {
        const int px = warp_n + (p * 2 + qhigh) * 8 + rowin;
        bRowB[p] = (uint32_t)(px + 8 * (px / 56)) * 128u;
    }
    {
        const int px7 = warp_n + 48 + rowin;
        bRowB[3] = (uint32_t)(px7 + 8 * (px7 / 56)) * 128u;
    }

    float acc[4][7][4];
    #pragma unroll
    for (int mi = 0; mi < 4; mi++)
        #pragma unroll
        for (int ni = 0; ni < 7; ni++)
            #pragma unroll
            for (int r = 0; r < 4; r++) acc[mi][ni][r] = 0.0f;

    {
        const long long F0 = ((long long)(n * 59 + h0) * 64 - 1) * CI;
        #pragma unroll
        for (int half = 0; half < 2; half++) {
            const __half* src = xb + F0 + half * 64;
            const uint32_t dstb = B_u + half * B_HALF_BYTES;
            for (int idx = tid; idx < 250 * 8; idx += 128) {
                const int i = idx >> 3, c = idx & 7;
                cp_async16(dstb + (uint32_t)i * 128u + (uint32_t)((c ^ (i & 7)) * 16),
                           src + (size_t)i * CI + c * 8);
            }
        }
    }

    auto loadA = [&](int kc) {
        const int tap = kc >> 1, cihalf = kc & 1;
        const __half* src = g_wt + (size_t)(tap * CO + co_base) * CI + cihalf * 64;
        const uint32_t dA = A_u + (kc & 1) * A_TILE;
        #pragma unroll
        for (int i = 0; i < 8; i++) {
            const int q = tid + 128 * i;
            const int row = q >> 3, c = q & 7;
            cp_async16(dA + (uint32_t)row * 128u + (uint32_t)((c ^ (row & 7)) * 16),
                       src + (size_t)row * CI + c * 8);
        }
    };

    loadA(0);
    CP_COMMIT();

    #pragma unroll
    for (int kc = 0; kc < 18; kc++) {
        const int tap = kc >> 1, cihalf = kc & 1;
        const int r = tap / 3, s = tap % 3;
        const int off = r * 64 + s;

        CP_WAIT0();
        __syncthreads();

        const uint32_t A  = A_u + (kc & 1) * A_TILE;
        const uint32_t Bo = B_u + cihalf * B_HALF_BYTES + (uint32_t)off * 128u;
        const int ro = (rowin + off) & 7;

        #pragma unroll
        for (int kk = 0; kk < 4; kk++) {
            uint32_t a[4][4];
            #pragma unroll
            for (int mi = 0; mi < 4; mi++)
                LDM_X4(a[mi][0], a[mi][1], a[mi][2], a[mi][3],
                       A + aRowB[mi] + (uint32_t)(((kk * 2 + qhigh) ^ rowin) * 16));
            #pragma unroll
            for (int p = 0; p < 3; p++) {
                uint32_t b0, b1, b2, b3;
                LDM_X4(b0, b1, b2, b3,
                       Bo + bRowB[p] + (uint32_t)(((kk * 2 + qlow) ^ ro) * 16));
                #pragma unroll
                for (int mi = 0; mi < 4; mi++) {
                    mma_f16(acc[mi][2 * p],     a[mi], b0, b1);
                    mma_f16(acc[mi][2 * p + 1], a[mi], b2, b3);
                }
            }
            {
                uint32_t b0, b1;
                LDM_X2(b0, b1,
                       Bo + bRowB[3] + (uint32_t)(((kk * 2 + qlow) ^ ro) * 16));
                #pragma unroll
                for (int mi = 0; mi < 4; mi++)
                    mma_f16(acc[mi][6], a[mi], b0, b1);
            }
            if (kk == 1) {
                if (kc + 1 < 18) loadA(kc + 1);
                CP_COMMIT();
            }
        }
        __syncthreads();
    }

    #pragma unroll
    for (int mi = 0; mi < 4; mi++)
        #pragma unroll
        for (int ni = 0; ni < 7; ni++)
            #pragma unroll
            for (int half = 0; half < 2; half++) {
                const int co = co_base + warp_m + mi * 16 + g + half * 8;
                const int px = warp_n + ni * 8 + 2 * t;
                const int dh = px / 56, w = px % 56;
                float2 v = make_float2(acc[mi][ni][half * 2], acc[mi][ni][half * 2 + 1]);
                *(float2*)&out[(((size_t)n * CO + co) * HH + (h0 + dh)) * WW + w] = v;
            }
}

// ---------------- host ----------------
extern "C" void kernel_launch(void* const* d_in, const int* in_sizes, int n_in,
                              void* d_out, int out_size)
{
    const float* x   = (const float*)d_in[0];
    const float* wgt = (const float*)d_in[1];
    float*       out = (float*)d_out;

    prologue_kernel<<<dim3(60, NNB), 256>>>(x, wgt);

    cudaFuncSetAttribute(conv_mma_kernel, cudaFuncAttributeMaxDynamicSharedMemorySize, SMEM_BYTES);
    conv_mma_kernel<<<dim3(2, 28, NNB), 128, SMEM_BYTES>>>(out);
}